// round 16
// baseline (speedup 1.0000x reference)
#include <cuda_runtime.h>
#include <cuda_fp16.h>
#include <cstdint>

// Problem constants (fixed by setup_inputs)
#define BSZ 256
#define SEQ 64
#define EMB 1024
#define HID 512
#define MAXN 127           // 2*S-1
#define NSTEP 63           // S-1
#define NCAT 511
#define SPST 520           // fp32 spec row stride (floats): 257 complex padded
#define SPH  544           // fp16 spec row stride (halfs): 514 padded to 17*32

typedef unsigned long long ull;

// ---------------- helpers ------------------------------------------------------
__device__ __forceinline__ uint32_t smem_u32(const void* p) {
    uint32_t a;
    asm("{ .reg .u64 t; cvta.to.shared.u64 t, %1; cvt.u32.u64 %0, t; }" : "=r"(a) : "l"(p));
    return a;
}
__device__ __forceinline__ void cpasync16(uint32_t dst, const void* src) {
    asm volatile("cp.async.cg.shared.global [%0], [%1], 16;" :: "r"(dst), "l"(src) : "memory");
}
__device__ __forceinline__ void ldsm4(uint32_t &d0, uint32_t &d1, uint32_t &d2, uint32_t &d3,
                                      uint32_t addr) {
    asm volatile("ldmatrix.sync.aligned.m8n8.x4.shared.b16 {%0,%1,%2,%3}, [%4];"
                 : "=r"(d0), "=r"(d1), "=r"(d2), "=r"(d3) : "r"(addr));
}
__device__ __forceinline__ void mma16816h(float* c, const uint32_t* a, uint32_t b0, uint32_t b1) {
    asm volatile("mma.sync.aligned.m16n8k16.row.col.f32.f16.f16.f32 "
                 "{%0,%1,%2,%3}, {%4,%5,%6,%7}, {%8,%9}, {%0,%1,%2,%3};"
                 : "+f"(c[0]), "+f"(c[1]), "+f"(c[2]), "+f"(c[3])
                 : "r"(a[0]), "r"(a[1]), "r"(a[2]), "r"(a[3]), "r"(b0), "r"(b1));
}
__device__ __forceinline__ void sts128(uint32_t addr, uint4 v) {
    asm volatile("st.shared.v4.b32 [%0], {%1,%2,%3,%4};"
                 :: "r"(addr), "r"(v.x), "r"(v.y), "r"(v.z), "r"(v.w) : "memory");
}
__device__ __forceinline__ uint32_t f2h2(float a, float b) {
    __half2 t = __float22half2_rn(make_float2(a, b));
    return *(uint32_t*)&t;
}
__device__ __forceinline__ uint4 round8h(float4 u, float4 v) {
    uint4 hi;
    hi.x = f2h2(u.x, u.y); hi.y = f2h2(u.z, u.w);
    hi.z = f2h2(v.x, v.y); hi.w = f2h2(v.z, v.w);
    return hi;
}

// ---------------- scratch (device globals: allocation-free) -------------------
__device__ __half g_comb[(size_t)BSZ * SEQ * HID];                // relu(GEMM1) fp16
__device__ __align__(16) float g_spec[(size_t)BSZ * MAXN * SPST]; // node spectra fp32
__device__ __half g_a2s[(size_t)BSZ * MAXN * SPH];                // node spectra fp16 (GEMM2 A)
__device__ __half g_b1h[(size_t)HID * EMB];                       // W^T fp16 [n][k]
__device__ __half g_lws[(size_t)512 * SPH];                       // weighted LW spectra fp16
__device__ float2 g_twf[128], g_w512f[256];

// ==============================================================================
__global__ void init_tables_kernel()
{
    int t = threadIdx.x;
    const float PI2 = 6.283185307179586f;
    if (t < 128) {
        float th = PI2 * t / 256.0f;
        float s, c; sincosf(th, &s, &c);
        g_twf[t] = make_float2(c, -s);
    }
    float ph = PI2 * t / 512.0f;
    float s, c; sincosf(ph, &s, &c);
    g_w512f[t] = make_float2(c, -s);
}

// coalesced tiled transpose: W1/W2 [k][n] -> g_b1h[n][k] fp16
__global__ void prep_b1_kernel(const float* __restrict__ W1, const float* __restrict__ W2)
{
    __shared__ float tile[32][33];
    const int kp0 = blockIdx.x * 32, n0 = blockIdx.y * 32;
    const int tx = threadIdx.x, ty = threadIdx.y;   // 32 x 8
#pragma unroll
    for (int i = 0; i < 32; i += 8) {
        int kp = kp0 + ty + i;
        const float* W = (kp < HID) ? (W1 + (size_t)kp * HID) : (W2 + (size_t)(kp - HID) * HID);
        tile[ty + i][tx] = W[n0 + tx];
    }
    __syncthreads();
#pragma unroll
    for (int i = 0; i < 32; i += 8) {
        int n = n0 + ty + i;
        g_b1h[(size_t)n * EMB + kp0 + tx] = __float2half_rn(tile[tx][ty + i]);
    }
}

// 512-pt rfft core (packed complex 256, DIF natural->bitrev), input in sZ.
__device__ __forceinline__ void fft256_dif(float2* sZ, const float2* stw, int tid)
{
#pragma unroll
    for (int s = 0; s < 8; s++) {
        const int half = 128 >> s;
        const int j = tid & (half - 1);
        const int p0 = (tid / half) * (half * 2) + j;
        const int p1 = p0 + half;
        float2 w = stw[j << s];
        float2 u = sZ[p0], vv = sZ[p1];
        sZ[p0] = make_float2(u.x + vv.x, u.y + vv.y);
        float dx = u.x - vv.x, dy = u.y - vv.y;
        sZ[p1] = make_float2(dx * w.x - dy * w.y, dx * w.y + dy * w.x);
        __syncthreads();
    }
}

// rfft of LW rows, weight-fold (Parseval), -> g_lws fp16 [n][544]
__global__ void __launch_bounds__(128) prep_lws_kernel(const float* __restrict__ LW)
{
    const int n = blockIdx.x;            // 0..511
    const int tid = threadIdx.x;
    uint32_t* sh = (uint32_t*)(g_lws + (size_t)n * SPH);

    if (n >= NCAT) {                      // pad row -> zeros
        sh[tid] = 0; sh[tid + 128] = 0;
        if (tid == 0) sh[256] = 0;
        return;
    }

    __shared__ float2 sZ[256];
    __shared__ float2 stw[128];
    __shared__ float2 sw5[256];
    stw[tid] = g_twf[tid];
    sw5[tid] = g_w512f[tid];
    sw5[tid + 128] = g_w512f[tid + 128];

    const float4* wr = (const float4*)(LW + (size_t)n * HID);
    float4 v = wr[tid];
    sZ[2*tid]     = make_float2(v.x, v.y);
    sZ[2*tid + 1] = make_float2(v.z, v.w);
    __syncthreads();

    fft256_dif(sZ, stw, tid);

    const float inv = 1.f / 512.f;
#pragma unroll
    for (int h = 0; h < 2; h++) {
        int k = tid + h * 128;
        int kb = __brev((unsigned)k) >> 24;
        int km = __brev((unsigned)((256 - k) & 255)) >> 24;
        float2 Zk = sZ[kb], Zm = sZ[km];
        float er = 0.5f * (Zk.x + Zm.x);
        float ei = 0.5f * (Zk.y - Zm.y);
        float orr = 0.5f * (Zk.y + Zm.y);
        float oii = -0.5f * (Zk.x - Zm.x);
        float2 w = sw5[k];
        float2 X = make_float2(er + w.x * orr - w.y * oii,
                               ei + w.x * oii + w.y * orr);
        float wt = (k == 0) ? inv : 2.f * inv;
        sh[k] = f2h2(wt * X.x, wt * X.y);
    }
    if (tid == 0) {
        float x256 = sZ[0].x - sZ[0].y;
        sh[256] = f2h2(inv * x256, 0.f);
    }
}

// ==============================================================================
// HMMA fp16 GEMM (proven config): 128 threads, warps 2m x 2n, 64x64 tiles,
// 3-stage cp.async ring, depth-2 prefetch, ONE __syncthreads per K-chunk.
// AMODE=0: A fp32 in gmem, fused round->fp16 in loader (LDG+STS).
// AMODE=1: A fp16 in gmem, cp.async.
// Stage (16KB): A@0, B@8K; 16B-chunk XOR swizzle.
// EPI=0: relu -> fp16 out. EPI=1: +bias -> fp32 out, n<NCAT guard.
// ==============================================================================
#define BM 128
#define BN 128
#define STGSZ 16384
#define NSTG 3

template<int AMODE, int EPI>
__global__ void __launch_bounds__(128, 2) mm_fp16_kernel(
    const float* __restrict__ Af, const __half* __restrict__ Ah,
    const __half* __restrict__ Bh,
    const float* __restrict__ bias, void* __restrict__ outv, int K, int ldo)
{
    extern __shared__ __align__(16) char smem[];
    const uint32_t sb = smem_u32(smem);

    const int tid  = threadIdx.x;
    const int lane = tid & 31;
    const int wid  = tid >> 5;           // 0..3
    const int wm   = (wid & 1) * 64;
    const int wn   = (wid >> 1) * 64;
    const int n0   = blockIdx.x * BN;
    const int m0   = blockIdx.y * BM;

    float acc[4][8][4];
#pragma unroll
    for (int mt = 0; mt < 4; mt++)
#pragma unroll
        for (int nt = 0; nt < 8; nt++)
#pragma unroll
            for (int i = 0; i < 4; i++) acc[mt][nt][i] = 0.f;

    // loader: 128 threads x 4 chunks cover one 8KB tile (512 x 16B)
    int lrow[4], lcc[4]; uint32_t lsw[4];
#pragma unroll
    for (int i = 0; i < 4; i++) {
        int idx = tid + i * 128;
        int row = idx >> 2, cc = idx & 3;
        lrow[i] = row; lcc[i] = cc;
        lsw[i] = row * 64 + ((cc ^ ((row >> 1) & 3)) << 4);
    }

    auto loadB = [&](int kt, uint32_t st) {
#pragma unroll
        for (int i = 0; i < 4; i++)
            cpasync16(st + 8192 + lsw[i], Bh + (size_t)(n0 + lrow[i]) * K + kt + lcc[i] * 8);
    };
    auto loadAasync = [&](int kt, uint32_t st) {
#pragma unroll
        for (int i = 0; i < 4; i++)
            cpasync16(st + lsw[i], Ah + (size_t)(m0 + lrow[i]) * K + kt + lcc[i] * 8);
    };

    float4 pr[8];                         // AMODE=0 prefetch: 4 chunks x 8 floats
    auto ldgA = [&](int kt) {
#pragma unroll
        for (int i = 0; i < 4; i++) {
            const float4* src = (const float4*)(Af + (size_t)(m0 + lrow[i]) * K + kt + lcc[i] * 8);
            pr[2*i]     = src[0];
            pr[2*i + 1] = src[1];
        }
    };
    auto cvtsts = [&](uint32_t st) {
#pragma unroll
        for (int i = 0; i < 4; i++)
            sts128(st + lsw[i], round8h(pr[2*i], pr[2*i + 1]));
    };

    const int C = K / 32;

    // prologue
    if (AMODE == 0) {
        ldgA(0);  cvtsts(sb + 0 * STGSZ);
        ldgA(32); cvtsts(sb + 1 * STGSZ);
        ldgA(64);
    }
    loadB(0, sb + 0 * STGSZ);
    if (AMODE == 1) loadAasync(0, sb + 0 * STGSZ);
    asm volatile("cp.async.commit_group;" ::: "memory");
    loadB(32, sb + 1 * STGSZ);
    if (AMODE == 1) loadAasync(32, sb + 1 * STGSZ);
    asm volatile("cp.async.commit_group;" ::: "memory");

    // ldmatrix constants
    const int rA  = wm + (lane & 15);
    const int hA  = lane >> 4;
    const int sAx = (rA >> 1) & 3;
    const int rB  = wn + (lane & 7) + ((lane >> 4) << 3);
    const int hB  = (lane >> 3) & 1;
    const int sBx = (rB >> 1) & 3;

    int s_cur = 0, s_nxt = 2;
    for (int c = 0; c < C; c++) {
        asm volatile("cp.async.wait_group 1;" ::: "memory");
        __syncthreads();

        const uint32_t st = sb + s_cur * STGSZ;
        const uint32_t nx = sb + s_nxt * STGSZ;
        if (c + 2 < C) {
            loadB((c + 2) * 32, nx);
            if (AMODE == 1) loadAasync((c + 2) * 32, nx);
            if (AMODE == 0) {
                cvtsts(nx);                         // chunk c+2 from pr
                if (c + 3 < C) ldgA((c + 3) * 32);
            }
        }
        asm volatile("cp.async.commit_group;" ::: "memory");

#pragma unroll
        for (int ks = 0; ks < 2; ks++) {
            const int chA = ((ks * 2 + hA) ^ sAx) << 4;
            const int chB = ((ks * 2 + hB) ^ sBx) << 4;
            uint32_t ah[4][4], bh[4][4];
#pragma unroll
            for (int mt = 0; mt < 4; mt++)
                ldsm4(ah[mt][0], ah[mt][1], ah[mt][2], ah[mt][3],
                      st + (rA + mt * 16) * 64 + chA);
#pragma unroll
            for (int g = 0; g < 4; g++)
                ldsm4(bh[g][0], bh[g][1], bh[g][2], bh[g][3],
                      st + 8192 + (rB + g * 16) * 64 + chB);
#pragma unroll
            for (int mt = 0; mt < 4; mt++)
#pragma unroll
                for (int nt = 0; nt < 8; nt++)
                    mma16816h(acc[mt][nt], ah[mt],
                              bh[nt >> 1][(nt & 1) * 2], bh[nt >> 1][(nt & 1) * 2 + 1]);
        }
        s_cur = (s_cur == 2) ? 0 : s_cur + 1;
        s_nxt = (s_nxt == 2) ? 0 : s_nxt + 1;
    }

    // epilogue
#pragma unroll
    for (int mt = 0; mt < 4; mt++) {
        const int mrow = m0 + wm + mt * 16 + (lane >> 2);
#pragma unroll
        for (int nt = 0; nt < 8; nt++) {
            const int ncol = n0 + wn + nt * 8 + 2 * (lane & 3);
            float* cc = acc[mt][nt];
            if (EPI == 0) {
                __half* outh = (__half*)outv;
                uint32_t p0 = f2h2(fmaxf(cc[0], 0.f), fmaxf(cc[1], 0.f));
                uint32_t p1 = f2h2(fmaxf(cc[2], 0.f), fmaxf(cc[3], 0.f));
                *(uint32_t*)(outh + (size_t)mrow * ldo + ncol) = p0;
                *(uint32_t*)(outh + (size_t)(mrow + 8) * ldo + ncol) = p1;
            } else {
                float* out = (float*)outv;
                if (ncol < NCAT) {
                    float bv = bias[ncol];
                    out[(size_t)mrow * ldo + ncol] = cc[0] + bv;
                    out[(size_t)(mrow + 8) * ldo + ncol] = cc[2] + bv;
                }
                if (ncol + 1 < NCAT) {
                    float bv = bias[ncol + 1];
                    out[(size_t)mrow * ldo + ncol + 1] = cc[1] + bv;
                    out[(size_t)(mrow + 8) * ldo + ncol + 1] = cc[3] + bv;
                }
            }
        }
    }
}

// ==============================================================================
// Leaf kernel: normalize comb row (fp16 in), rfft -> g_spec (fp32) + g_a2s (fp16).
// ==============================================================================
__global__ void __launch_bounds__(128) leaf_kernel(const int* __restrict__ opos)
{
    const int row = blockIdx.x;          // 0..16383
    const int b = row >> 6;
    const int dst = opos[(row << 1) + 0];
    const int src = opos[(row << 1) + 1];
    const int tid = threadIdx.x;

    __shared__ float2 sZ[256];
    __shared__ float2 stw[128];
    __shared__ float2 sw5[256];
    __shared__ float ws[4];

    stw[tid] = g_twf[tid];
    sw5[tid] = g_w512f[tid];
    sw5[tid + 128] = g_w512f[tid + 128];

    const uint2* cp = (const uint2*)(g_comb + ((size_t)(b * SEQ + src)) * HID);
    uint2 hv = cp[tid];
    float2 a01 = __half22float2(*(__half2*)&hv.x);
    float2 a23 = __half22float2(*(__half2*)&hv.y);
    float4 v = make_float4(a01.x, a01.y, a23.x, a23.y);
    float ss = v.x*v.x + v.y*v.y + v.z*v.z + v.w*v.w;
#pragma unroll
    for (int o = 16; o; o >>= 1) ss += __shfl_xor_sync(0xffffffffu, ss, o);
    if ((tid & 31) == 0) ws[tid >> 5] = ss;
    __syncthreads();
    float sc = 1.f / (sqrtf(ws[0] + ws[1] + ws[2] + ws[3]) + 1e-6f);
    v = make_float4(v.x*sc, v.y*sc, v.z*sc, v.w*sc);

    sZ[2*tid]     = make_float2(v.x, v.y);
    sZ[2*tid + 1] = make_float2(v.z, v.w);
    __syncthreads();

    fft256_dif(sZ, stw, tid);

    const size_t nrow = (size_t)(b * MAXN + dst);
    float* spec = g_spec + nrow * SPST;
    uint32_t* sh = (uint32_t*)(g_a2s + nrow * SPH);
#pragma unroll
    for (int h = 0; h < 2; h++) {
        int k = tid + h * 128;
        int kb = __brev((unsigned)k) >> 24;
        int km = __brev((unsigned)((256 - k) & 255)) >> 24;
        float2 Zk = sZ[kb], Zm = sZ[km];
        float er = 0.5f * (Zk.x + Zm.x);
        float ei = 0.5f * (Zk.y - Zm.y);
        float orr = 0.5f * (Zk.y + Zm.y);
        float oii = -0.5f * (Zk.x - Zm.x);
        float2 w = sw5[k];
        float2 X = make_float2(er + w.x * orr - w.y * oii,
                               ei + w.x * oii + w.y * orr);
        *(float2*)(spec + 2 * k) = X;
        sh[k] = f2h2(X.x, X.y);
    }
    if (tid == 0) {
        float x256 = sZ[0].x - sZ[0].y;
        *(float2*)(spec + 512) = make_float2(x256, 0.f);
        sh[256] = f2h2(x256, 0.f);
    }
}

// ==============================================================================
// Chain (spectral): 2 batches per 256-thread block (half-block each), 63 steps.
// F in registers; G double-buffered via cp.async from fp32 spec.
// Writes fp32 spec (chain/fallback) + fp16 spec (GEMM2 A).
// ==============================================================================
__global__ void __launch_bounds__(256) chain_spec_kernel(const int* __restrict__ cinfo)
{
    __shared__ __align__(16) float2 sG[2][2][260];   // [half][buf][260]
    __shared__ float ws[2][4];
    __shared__ int sInfo[2][NSTEP * 4];

    const int tid  = threadIdx.x;
    const int half = tid >> 7;
    const int ltid = tid & 127;
    const int b = blockIdx.x * 2 + half;
    const size_t nbase = (size_t)b * MAXN;

    for (int i = ltid; i < NSTEP * 4; i += 128)
        sInfo[half][i] = cinfo[(size_t)b * NSTEP * 4 + i];
    __syncthreads();

    float2 F0, F1, F2 = make_float2(0.f, 0.f);
    {
        int l0 = sInfo[half][2];
        const float2* fr = (const float2*)(g_spec + (nbase + l0) * SPST);
        F0 = fr[ltid]; F1 = fr[ltid + 128];
        if (ltid == 0) F2 = fr[256];
    }
    int prev_p = sInfo[half][2];

    {
        const float* src = g_spec + (nbase + sInfo[half][3]) * SPST;
        uint32_t dst = smem_u32(&sG[half][0][0]);
        cpasync16(dst + ltid * 16, src + ltid * 4);
        if (ltid < 2) cpasync16(dst + (128 + ltid) * 16, src + (128 + ltid) * 4);
        asm volatile("cp.async.commit_group;" ::: "memory");
    }

    for (int k = 0; k < NSTEP; k++) {
        const int t = sInfo[half][k*4 + 0];
        const int p = sInfo[half][k*4 + 1];
        const int l = sInfo[half][k*4 + 2];
        const int cb = k & 1;

        bool issued = false;
        if (k + 1 < NSTEP) {
            const float* src = g_spec + (nbase + sInfo[half][(k+1)*4 + 3]) * SPST;
            uint32_t dst = smem_u32(&sG[half][cb ^ 1][0]);
            cpasync16(dst + ltid * 16, src + ltid * 4);
            if (ltid < 2) cpasync16(dst + (128 + ltid) * 16, src + (128 + ltid) * 4);
            asm volatile("cp.async.commit_group;" ::: "memory");
            issued = true;
        }
        if (issued) asm volatile("cp.async.wait_group 1;" ::: "memory");
        else        asm volatile("cp.async.wait_group 0;" ::: "memory");
        __syncthreads();

        if (l != prev_p) {
            const float2* fr = (const float2*)(g_spec + (nbase + l) * SPST);
            F0 = fr[ltid]; F1 = fr[ltid + 128];
            if (ltid == 0) F2 = fr[256];
        }
        float2 G0 = sG[half][cb][ltid];
        float2 G1 = sG[half][cb][ltid + 128];

        float* specP = g_spec + (nbase + p) * SPST;
        uint32_t* shP = (uint32_t*)(g_a2s + (nbase + p) * SPH);

        if (t == 2) {
            float2 c0 = make_float2(F0.x*G0.x + F0.y*G0.y, F0.x*G0.y - F0.y*G0.x);
            float2 c1 = make_float2(F1.x*G1.x + F1.y*G1.y, F1.x*G1.y - F1.y*G1.x);
            float w0 = (ltid == 0) ? 1.f : 2.f;
            float part = w0 * (c0.x*c0.x + c0.y*c0.y) + 2.f * (c1.x*c1.x + c1.y*c1.y);
            float2 c2 = make_float2(0.f, 0.f);
            if (ltid == 0) {
                float2 G2 = sG[half][cb][256];
                c2 = make_float2(F2.x*G2.x + F2.y*G2.y, F2.x*G2.y - F2.y*G2.x);
                part += c2.x*c2.x + c2.y*c2.y;
            }
#pragma unroll
            for (int o = 16; o; o >>= 1) part += __shfl_xor_sync(0xffffffffu, part, o);
            if ((ltid & 31) == 0) ws[half][ltid >> 5] = part;
            __syncthreads();
            float s = 1.f / (sqrtf((ws[half][0] + ws[half][1] + ws[half][2] + ws[half][3])
                                   * (1.f / 512.f)) + 1e-6f);

            F0 = make_float2(s * c0.x, s * c0.y);
            F1 = make_float2(s * c1.x, s * c1.y);
            *(float2*)(specP + 2 * ltid) = F0;
            *(float2*)(specP + 2 * (ltid + 128)) = F1;
            shP[ltid] = f2h2(F0.x, F0.y);
            shP[ltid + 128] = f2h2(F1.x, F1.y);
            if (ltid == 0) {
                F2 = make_float2(s * c2.x, s * c2.y);
                *(float2*)(specP + 512) = F2;
                shP[256] = f2h2(F2.x, F2.y);
            }
        } else if (t == 1) {
            *(float2*)(specP + 2 * ltid) = F0;
            *(float2*)(specP + 2 * (ltid + 128)) = F1;
            shP[ltid] = f2h2(F0.x, F0.y);
            shP[ltid + 128] = f2h2(F1.x, F1.y);
            if (ltid == 0) {
                *(float2*)(specP + 512) = F2;
                shP[256] = f2h2(F2.x, F2.y);
            }
        } else {
            float2 z = make_float2(0.f, 0.f);
            F0 = z; F1 = z; F2 = z;
            *(float2*)(specP + 2 * ltid) = z;
            *(float2*)(specP + 2 * (ltid + 128)) = z;
            shP[ltid] = 0; shP[ltid + 128] = 0;
            if (ltid == 0) { *(float2*)(specP + 512) = z; shP[256] = 0; }
        }
        prev_p = p;
        __syncthreads();
    }
}

// ==============================================================================
extern "C" void kernel_launch(void* const* d_in, const int* in_sizes, int n_in,
                              void* d_out, int out_size)
{
    const float* seq  = (const float*)d_in[0];   // (256,64,1024)
    const float* W1   = (const float*)d_in[1];   // (512,512)
    const float* W2   = (const float*)d_in[2];   // (512,512)
    const float* LW   = (const float*)d_in[3];   // (511,512)
    const float* LB   = (const float*)d_in[4];   // (511,)
    const int*   opos = (const int*)d_in[7];     // (256,64,2)
    const int*   cinf = (const int*)d_in[8];     // (256,63,4)
    float* out = (float*)d_out;                  // (256,127,511)

    __half *comb, *a2s, *b1h, *lws;
    cudaGetSymbolAddress((void**)&comb, g_comb);
    cudaGetSymbolAddress((void**)&a2s, g_a2s);
    cudaGetSymbolAddress((void**)&b1h, g_b1h);
    cudaGetSymbolAddress((void**)&lws, g_lws);

    cudaFuncSetAttribute(mm_fp16_kernel<0, 0>,
                         cudaFuncAttributeMaxDynamicSharedMemorySize, NSTG * STGSZ);
    cudaFuncSetAttribute(mm_fp16_kernel<1, 1>,
                         cudaFuncAttributeMaxDynamicSharedMemorySize, NSTG * STGSZ);

    init_tables_kernel<<<1, 256>>>();
    {
        dim3 b(32, 8);
        dim3 g(EMB / 32, HID / 32);
        prep_b1_kernel<<<g, b>>>(W1, W2);
    }
    prep_lws_kernel<<<512, 128>>>(LW);

    // GEMM1: comb = relu(seq @ [W1;W2]) -> fp16; fused fp32->fp16 A convert
    {
        dim3 g(HID / BN, BSZ * SEQ / BM);         // (4, 128)
        mm_fp16_kernel<0, 0><<<g, 128, NSTG * STGSZ>>>(
            seq, nullptr, b1h, nullptr, comb, EMB, HID);
    }

    leaf_kernel<<<BSZ * SEQ, 128>>>(opos);
    chain_spec_kernel<<<BSZ / 2, 256>>>(cinf);

    // GEMM2 in frequency domain: out[m,n] = <spec_m, wspec_n> + LB[n], K=544
    {
        dim3 g(512 / BN, BSZ * MAXN / BM);        // (4, 254)
        mm_fp16_kernel<1, 1><<<g, 128, NSTG * STGSZ>>>(
            nullptr, a2s, lws, LB, out, SPH, NCAT);
    }
}

// round 17
// speedup vs baseline: 1.0187x; 1.0187x over previous
#include <cuda_runtime.h>
#include <cuda_fp16.h>
#include <cstdint>

// Problem constants (fixed by setup_inputs)
#define BSZ 256
#define SEQ 64
#define EMB 1024
#define HID 512
#define MAXN 127           // 2*S-1
#define NSTEP 63           // S-1
#define NCAT 511
#define SPST 520           // fp32 spec row stride (floats): 257 complex padded
#define SPH  544           // fp16 spec row stride (halfs): 514 padded to 17*32

typedef unsigned long long ull;

// ---------------- helpers ------------------------------------------------------
__device__ __forceinline__ uint32_t smem_u32(const void* p) {
    uint32_t a;
    asm("{ .reg .u64 t; cvta.to.shared.u64 t, %1; cvt.u32.u64 %0, t; }" : "=r"(a) : "l"(p));
    return a;
}
__device__ __forceinline__ void cpasync16(uint32_t dst, const void* src) {
    asm volatile("cp.async.cg.shared.global [%0], [%1], 16;" :: "r"(dst), "l"(src) : "memory");
}
__device__ __forceinline__ void ldsm4(uint32_t &d0, uint32_t &d1, uint32_t &d2, uint32_t &d3,
                                      uint32_t addr) {
    asm volatile("ldmatrix.sync.aligned.m8n8.x4.shared.b16 {%0,%1,%2,%3}, [%4];"
                 : "=r"(d0), "=r"(d1), "=r"(d2), "=r"(d3) : "r"(addr));
}
__device__ __forceinline__ void mma16816h(float* c, const uint32_t* a, uint32_t b0, uint32_t b1) {
    asm volatile("mma.sync.aligned.m16n8k16.row.col.f32.f16.f16.f32 "
                 "{%0,%1,%2,%3}, {%4,%5,%6,%7}, {%8,%9}, {%0,%1,%2,%3};"
                 : "+f"(c[0]), "+f"(c[1]), "+f"(c[2]), "+f"(c[3])
                 : "r"(a[0]), "r"(a[1]), "r"(a[2]), "r"(a[3]), "r"(b0), "r"(b1));
}
__device__ __forceinline__ uint32_t f2h2(float a, float b) {
    __half2 t = __float22half2_rn(make_float2(a, b));
    return *(uint32_t*)&t;
}

// ---------------- scratch (device globals: allocation-free) -------------------
__device__ __half g_comb[(size_t)BSZ * SEQ * HID];                // relu(GEMM1) fp16
__device__ __align__(16) float g_spec[(size_t)BSZ * MAXN * SPST]; // node spectra fp32
__device__ __half g_a1h[(size_t)BSZ * SEQ * EMB];                 // seq fp16
__device__ __half g_a2s[(size_t)BSZ * MAXN * SPH];                // node spectra fp16 (GEMM2 A)
__device__ __half g_b1h[(size_t)HID * EMB];                       // W^T fp16 [n][k]
__device__ __half g_lws[(size_t)512 * SPH];                       // weighted LW spectra fp16
__device__ float2 g_twf[128], g_w512f[256];

// ==============================================================================
__global__ void init_tables_kernel()
{
    int t = threadIdx.x;
    const float PI2 = 6.283185307179586f;
    if (t < 128) {
        float th = PI2 * t / 256.0f;
        float s, c; sincosf(th, &s, &c);
        g_twf[t] = make_float2(c, -s);
    }
    float ph = PI2 * t / 512.0f;
    float s, c; sincosf(ph, &s, &c);
    g_w512f[t] = make_float2(c, -s);
}

// seq fp32 -> fp16 (streaming convert)
__global__ void prep_a1_kernel(const float* __restrict__ seq)
{
    size_t idx = (size_t)blockIdx.x * 256 + threadIdx.x;   // float4 index
    float4 v = ((const float4*)seq)[idx];
    uint2 o;
    o.x = f2h2(v.x, v.y);
    o.y = f2h2(v.z, v.w);
    ((uint2*)g_a1h)[idx] = o;
}

// coalesced tiled transpose: W1/W2 [k][n] -> g_b1h[n][k] fp16
__global__ void prep_b1_kernel(const float* __restrict__ W1, const float* __restrict__ W2)
{
    __shared__ float tile[32][33];
    const int kp0 = blockIdx.x * 32, n0 = blockIdx.y * 32;
    const int tx = threadIdx.x, ty = threadIdx.y;   // 32 x 8
#pragma unroll
    for (int i = 0; i < 32; i += 8) {
        int kp = kp0 + ty + i;
        const float* W = (kp < HID) ? (W1 + (size_t)kp * HID) : (W2 + (size_t)(kp - HID) * HID);
        tile[ty + i][tx] = W[n0 + tx];
    }
    __syncthreads();
#pragma unroll
    for (int i = 0; i < 32; i += 8) {
        int n = n0 + ty + i;
        g_b1h[(size_t)n * EMB + kp0 + tx] = __float2half_rn(tile[tx][ty + i]);
    }
}

// 512-pt rfft core (packed complex 256, DIF natural->bitrev), input in sZ.
__device__ __forceinline__ void fft256_dif(float2* sZ, const float2* stw, int tid)
{
#pragma unroll
    for (int s = 0; s < 8; s++) {
        const int half = 128 >> s;
        const int j = tid & (half - 1);
        const int p0 = (tid / half) * (half * 2) + j;
        const int p1 = p0 + half;
        float2 w = stw[j << s];
        float2 u = sZ[p0], vv = sZ[p1];
        sZ[p0] = make_float2(u.x + vv.x, u.y + vv.y);
        float dx = u.x - vv.x, dy = u.y - vv.y;
        sZ[p1] = make_float2(dx * w.x - dy * w.y, dx * w.y + dy * w.x);
        __syncthreads();
    }
}

// rfft of LW rows, weight-fold (Parseval), -> g_lws fp16 [n][544]
// NOTE: computes its own twiddles (no dependency on init_tables) so it can
// run on a parallel graph branch.
__global__ void __launch_bounds__(128) prep_lws_kernel(const float* __restrict__ LW)
{
    const int n = blockIdx.x;            // 0..511
    const int tid = threadIdx.x;
    uint32_t* sh = (uint32_t*)(g_lws + (size_t)n * SPH);

    if (n >= NCAT) {                      // pad row -> zeros
        sh[tid] = 0; sh[tid + 128] = 0;
        if (tid == 0) sh[256] = 0;
        return;
    }

    __shared__ float2 sZ[256];
    __shared__ float2 stw[128];
    __shared__ float2 sw5[256];
    {
        const float PI2 = 6.283185307179586f;
        float s, c;
        sincosf(PI2 * tid / 256.0f, &s, &c);
        stw[tid] = make_float2(c, -s);
        sincosf(PI2 * tid / 512.0f, &s, &c);
        sw5[tid] = make_float2(c, -s);
        sincosf(PI2 * (tid + 128) / 512.0f, &s, &c);
        sw5[tid + 128] = make_float2(c, -s);
    }

    const float4* wr = (const float4*)(LW + (size_t)n * HID);
    float4 v = wr[tid];
    sZ[2*tid]     = make_float2(v.x, v.y);
    sZ[2*tid + 1] = make_float2(v.z, v.w);
    __syncthreads();

    fft256_dif(sZ, stw, tid);

    const float inv = 1.f / 512.f;
#pragma unroll
    for (int h = 0; h < 2; h++) {
        int k = tid + h * 128;
        int kb = __brev((unsigned)k) >> 24;
        int km = __brev((unsigned)((256 - k) & 255)) >> 24;
        float2 Zk = sZ[kb], Zm = sZ[km];
        float er = 0.5f * (Zk.x + Zm.x);
        float ei = 0.5f * (Zk.y - Zm.y);
        float orr = 0.5f * (Zk.y + Zm.y);
        float oii = -0.5f * (Zk.x - Zm.x);
        float2 w = sw5[k];
        float2 X = make_float2(er + w.x * orr - w.y * oii,
                               ei + w.x * oii + w.y * orr);
        float wt = (k == 0) ? inv : 2.f * inv;
        sh[k] = f2h2(wt * X.x, wt * X.y);
    }
    if (tid == 0) {
        float x256 = sZ[0].x - sZ[0].y;
        sh[256] = f2h2(inv * x256, 0.f);
    }
}

// ==============================================================================
// HMMA fp16 GEMM (proven config): 128 threads, warps 2m x 2n, 64x64 tiles,
// 3-stage cp.async ring, depth-2 prefetch, ONE __syncthreads per K-chunk.
// Stage (16KB): A@0, B@8K; 16B-chunk XOR swizzle.
// EPI=0: relu -> fp16 out. EPI=1: +bias -> fp32 out, n<NCAT guard.
// ==============================================================================
#define BM 128
#define BN 128
#define STGSZ 16384
#define NSTG 3

template<int EPI>
__global__ void __launch_bounds__(128, 2) mm_fp16_kernel(
    const __half* __restrict__ Ah, const __half* __restrict__ Bh,
    const float* __restrict__ bias, void* __restrict__ outv, int K, int ldo)
{
    extern __shared__ __align__(16) char smem[];
    const uint32_t sb = smem_u32(smem);

    const int tid  = threadIdx.x;
    const int lane = tid & 31;
    const int wid  = tid >> 5;           // 0..3
    const int wm   = (wid & 1) * 64;
    const int wn   = (wid >> 1) * 64;
    const int n0   = blockIdx.x * BN;
    const int m0   = blockIdx.y * BM;

    float acc[4][8][4];
#pragma unroll
    for (int mt = 0; mt < 4; mt++)
#pragma unroll
        for (int nt = 0; nt < 8; nt++)
#pragma unroll
            for (int i = 0; i < 4; i++) acc[mt][nt][i] = 0.f;

    // loader: 128 threads x 4 chunks cover one 8KB tile (512 x 16B)
    int lrow[4], lcc[4]; uint32_t lsw[4];
#pragma unroll
    for (int i = 0; i < 4; i++) {
        int idx = tid + i * 128;
        int row = idx >> 2, cc = idx & 3;
        lrow[i] = row; lcc[i] = cc;
        lsw[i] = row * 64 + ((cc ^ ((row >> 1) & 3)) << 4);
    }

    auto loadTile = [&](int kt, uint32_t st) {
#pragma unroll
        for (int i = 0; i < 4; i++) {
            cpasync16(st + lsw[i],        Ah + (size_t)(m0 + lrow[i]) * K + kt + lcc[i] * 8);
            cpasync16(st + 8192 + lsw[i], Bh + (size_t)(n0 + lrow[i]) * K + kt + lcc[i] * 8);
        }
    };

    const int C = K / 32;

    loadTile(0, sb + 0 * STGSZ);
    asm volatile("cp.async.commit_group;" ::: "memory");
    loadTile(32, sb + 1 * STGSZ);
    asm volatile("cp.async.commit_group;" ::: "memory");

    // ldmatrix constants
    const int rA  = wm + (lane & 15);
    const int hA  = lane >> 4;
    const int sAx = (rA >> 1) & 3;
    const int rB  = wn + (lane & 7) + ((lane >> 4) << 3);
    const int hB  = (lane >> 3) & 1;
    const int sBx = (rB >> 1) & 3;

    int s_cur = 0, s_nxt = 2;
    for (int c = 0; c < C; c++) {
        asm volatile("cp.async.wait_group 1;" ::: "memory");
        __syncthreads();

        const uint32_t st = sb + s_cur * STGSZ;
        const uint32_t nx = sb + s_nxt * STGSZ;
        if (c + 2 < C) loadTile((c + 2) * 32, nx);
        asm volatile("cp.async.commit_group;" ::: "memory");

#pragma unroll
        for (int ks = 0; ks < 2; ks++) {
            const int chA = ((ks * 2 + hA) ^ sAx) << 4;
            const int chB = ((ks * 2 + hB) ^ sBx) << 4;
            uint32_t ah[4][4], bh[4][4];
#pragma unroll
            for (int mt = 0; mt < 4; mt++)
                ldsm4(ah[mt][0], ah[mt][1], ah[mt][2], ah[mt][3],
                      st + (rA + mt * 16) * 64 + chA);
#pragma unroll
            for (int g = 0; g < 4; g++)
                ldsm4(bh[g][0], bh[g][1], bh[g][2], bh[g][3],
                      st + 8192 + (rB + g * 16) * 64 + chB);
#pragma unroll
            for (int mt = 0; mt < 4; mt++)
#pragma unroll
                for (int nt = 0; nt < 8; nt++)
                    mma16816h(acc[mt][nt], ah[mt],
                              bh[nt >> 1][(nt & 1) * 2], bh[nt >> 1][(nt & 1) * 2 + 1]);
        }
        s_cur = (s_cur == 2) ? 0 : s_cur + 1;
        s_nxt = (s_nxt == 2) ? 0 : s_nxt + 1;
    }

    // epilogue
#pragma unroll
    for (int mt = 0; mt < 4; mt++) {
        const int mrow = m0 + wm + mt * 16 + (lane >> 2);
#pragma unroll
        for (int nt = 0; nt < 8; nt++) {
            const int ncol = n0 + wn + nt * 8 + 2 * (lane & 3);
            float* cc = acc[mt][nt];
            if (EPI == 0) {
                __half* outh = (__half*)outv;
                uint32_t p0 = f2h2(fmaxf(cc[0], 0.f), fmaxf(cc[1], 0.f));
                uint32_t p1 = f2h2(fmaxf(cc[2], 0.f), fmaxf(cc[3], 0.f));
                *(uint32_t*)(outh + (size_t)mrow * ldo + ncol) = p0;
                *(uint32_t*)(outh + (size_t)(mrow + 8) * ldo + ncol) = p1;
            } else {
                float* out = (float*)outv;
                if (ncol < NCAT) {
                    float bv = bias[ncol];
                    out[(size_t)mrow * ldo + ncol] = cc[0] + bv;
                    out[(size_t)(mrow + 8) * ldo + ncol] = cc[2] + bv;
                }
                if (ncol + 1 < NCAT) {
                    float bv = bias[ncol + 1];
                    out[(size_t)mrow * ldo + ncol + 1] = cc[1] + bv;
                    out[(size_t)(mrow + 8) * ldo + ncol + 1] = cc[3] + bv;
                }
            }
        }
    }
}

// ==============================================================================
// Leaf kernel: normalize comb row (fp16 in), rfft -> g_spec (fp32) + g_a2s (fp16).
// ==============================================================================
__global__ void __launch_bounds__(128) leaf_kernel(const int* __restrict__ opos)
{
    const int row = blockIdx.x;          // 0..16383
    const int b = row >> 6;
    const int dst = opos[(row << 1) + 0];
    const int src = opos[(row << 1) + 1];
    const int tid = threadIdx.x;

    __shared__ float2 sZ[256];
    __shared__ float2 stw[128];
    __shared__ float2 sw5[256];
    __shared__ float ws[4];

    stw[tid] = g_twf[tid];
    sw5[tid] = g_w512f[tid];
    sw5[tid + 128] = g_w512f[tid + 128];

    const uint2* cp = (const uint2*)(g_comb + ((size_t)(b * SEQ + src)) * HID);
    uint2 hv = cp[tid];
    float2 a01 = __half22float2(*(__half2*)&hv.x);
    float2 a23 = __half22float2(*(__half2*)&hv.y);
    float4 v = make_float4(a01.x, a01.y, a23.x, a23.y);
    float ss = v.x*v.x + v.y*v.y + v.z*v.z + v.w*v.w;
#pragma unroll
    for (int o = 16; o; o >>= 1) ss += __shfl_xor_sync(0xffffffffu, ss, o);
    if ((tid & 31) == 0) ws[tid >> 5] = ss;
    __syncthreads();
    float sc = 1.f / (sqrtf(ws[0] + ws[1] + ws[2] + ws[3]) + 1e-6f);
    v = make_float4(v.x*sc, v.y*sc, v.z*sc, v.w*sc);

    sZ[2*tid]     = make_float2(v.x, v.y);
    sZ[2*tid + 1] = make_float2(v.z, v.w);
    __syncthreads();

    fft256_dif(sZ, stw, tid);

    const size_t nrow = (size_t)(b * MAXN + dst);
    float* spec = g_spec + nrow * SPST;
    uint32_t* sh = (uint32_t*)(g_a2s + nrow * SPH);
#pragma unroll
    for (int h = 0; h < 2; h++) {
        int k = tid + h * 128;
        int kb = __brev((unsigned)k) >> 24;
        int km = __brev((unsigned)((256 - k) & 255)) >> 24;
        float2 Zk = sZ[kb], Zm = sZ[km];
        float er = 0.5f * (Zk.x + Zm.x);
        float ei = 0.5f * (Zk.y - Zm.y);
        float orr = 0.5f * (Zk.y + Zm.y);
        float oii = -0.5f * (Zk.x - Zm.x);
        float2 w = sw5[k];
        float2 X = make_float2(er + w.x * orr - w.y * oii,
                               ei + w.x * oii + w.y * orr);
        *(float2*)(spec + 2 * k) = X;
        sh[k] = f2h2(X.x, X.y);
    }
    if (tid == 0) {
        float x256 = sZ[0].x - sZ[0].y;
        *(float2*)(spec + 512) = make_float2(x256, 0.f);
        sh[256] = f2h2(x256, 0.f);
    }
}

// ==============================================================================
// Chain (spectral): 2 batches per 256-thread block (half-block each), 63 steps.
// F in registers; G double-buffered via cp.async from fp32 spec.
// ==============================================================================
__global__ void __launch_bounds__(256) chain_spec_kernel(const int* __restrict__ cinfo)
{
    __shared__ __align__(16) float2 sG[2][2][260];   // [half][buf][260]
    __shared__ float ws[2][4];
    __shared__ int sInfo[2][NSTEP * 4];

    const int tid  = threadIdx.x;
    const int half = tid >> 7;
    const int ltid = tid & 127;
    const int b = blockIdx.x * 2 + half;
    const size_t nbase = (size_t)b * MAXN;

    for (int i = ltid; i < NSTEP * 4; i += 128)
        sInfo[half][i] = cinfo[(size_t)b * NSTEP * 4 + i];
    __syncthreads();

    float2 F0, F1, F2 = make_float2(0.f, 0.f);
    {
        int l0 = sInfo[half][2];
        const float2* fr = (const float2*)(g_spec + (nbase + l0) * SPST);
        F0 = fr[ltid]; F1 = fr[ltid + 128];
        if (ltid == 0) F2 = fr[256];
    }
    int prev_p = sInfo[half][2];

    {
        const float* src = g_spec + (nbase + sInfo[half][3]) * SPST;
        uint32_t dst = smem_u32(&sG[half][0][0]);
        cpasync16(dst + ltid * 16, src + ltid * 4);
        if (ltid < 2) cpasync16(dst + (128 + ltid) * 16, src + (128 + ltid) * 4);
        asm volatile("cp.async.commit_group;" ::: "memory");
    }

    for (int k = 0; k < NSTEP; k++) {
        const int t = sInfo[half][k*4 + 0];
        const int p = sInfo[half][k*4 + 1];
        const int l = sInfo[half][k*4 + 2];
        const int cb = k & 1;

        bool issued = false;
        if (k + 1 < NSTEP) {
            const float* src = g_spec + (nbase + sInfo[half][(k+1)*4 + 3]) * SPST;
            uint32_t dst = smem_u32(&sG[half][cb ^ 1][0]);
            cpasync16(dst + ltid * 16, src + ltid * 4);
            if (ltid < 2) cpasync16(dst + (128 + ltid) * 16, src + (128 + ltid) * 4);
            asm volatile("cp.async.commit_group;" ::: "memory");
            issued = true;
        }
        if (issued) asm volatile("cp.async.wait_group 1;" ::: "memory");
        else        asm volatile("cp.async.wait_group 0;" ::: "memory");
        __syncthreads();

        if (l != prev_p) {
            const float2* fr = (const float2*)(g_spec + (nbase + l) * SPST);
            F0 = fr[ltid]; F1 = fr[ltid + 128];
            if (ltid == 0) F2 = fr[256];
        }
        float2 G0 = sG[half][cb][ltid];
        float2 G1 = sG[half][cb][ltid + 128];

        float* specP = g_spec + (nbase + p) * SPST;
        uint32_t* shP = (uint32_t*)(g_a2s + (nbase + p) * SPH);

        if (t == 2) {
            float2 c0 = make_float2(F0.x*G0.x + F0.y*G0.y, F0.x*G0.y - F0.y*G0.x);
            float2 c1 = make_float2(F1.x*G1.x + F1.y*G1.y, F1.x*G1.y - F1.y*G1.x);
            float w0 = (ltid == 0) ? 1.f : 2.f;
            float part = w0 * (c0.x*c0.x + c0.y*c0.y) + 2.f * (c1.x*c1.x + c1.y*c1.y);
            float2 c2 = make_float2(0.f, 0.f);
            if (ltid == 0) {
                float2 G2 = sG[half][cb][256];
                c2 = make_float2(F2.x*G2.x + F2.y*G2.y, F2.x*G2.y - F2.y*G2.x);
                part += c2.x*c2.x + c2.y*c2.y;
            }
#pragma unroll
            for (int o = 16; o; o >>= 1) part += __shfl_xor_sync(0xffffffffu, part, o);
            if ((ltid & 31) == 0) ws[half][ltid >> 5] = part;
            __syncthreads();
            float s = 1.f / (sqrtf((ws[half][0] + ws[half][1] + ws[half][2] + ws[half][3])
                                   * (1.f / 512.f)) + 1e-6f);

            F0 = make_float2(s * c0.x, s * c0.y);
            F1 = make_float2(s * c1.x, s * c1.y);
            *(float2*)(specP + 2 * ltid) = F0;
            *(float2*)(specP + 2 * (ltid + 128)) = F1;
            shP[ltid] = f2h2(F0.x, F0.y);
            shP[ltid + 128] = f2h2(F1.x, F1.y);
            if (ltid == 0) {
                F2 = make_float2(s * c2.x, s * c2.y);
                *(float2*)(specP + 512) = F2;
                shP[256] = f2h2(F2.x, F2.y);
            }
        } else if (t == 1) {
            *(float2*)(specP + 2 * ltid) = F0;
            *(float2*)(specP + 2 * (ltid + 128)) = F1;
            shP[ltid] = f2h2(F0.x, F0.y);
            shP[ltid + 128] = f2h2(F1.x, F1.y);
            if (ltid == 0) {
                *(float2*)(specP + 512) = F2;
                shP[256] = f2h2(F2.x, F2.y);
            }
        } else {
            float2 z = make_float2(0.f, 0.f);
            F0 = z; F1 = z; F2 = z;
            *(float2*)(specP + 2 * ltid) = z;
            *(float2*)(specP + 2 * (ltid + 128)) = z;
            shP[ltid] = 0; shP[ltid + 128] = 0;
            if (ltid == 0) { *(float2*)(specP + 512) = z; shP[256] = 0; }
        }
        prev_p = p;
        __syncthreads();
    }
}

// ==============================================================================
extern "C" void kernel_launch(void* const* d_in, const int* in_sizes, int n_in,
                              void* d_out, int out_size)
{
    const float* seq  = (const float*)d_in[0];   // (256,64,1024)
    const float* W1   = (const float*)d_in[1];   // (512,512)
    const float* W2   = (const float*)d_in[2];   // (512,512)
    const float* LW   = (const float*)d_in[3];   // (511,512)
    const float* LB   = (const float*)d_in[4];   // (511,)
    const int*   opos = (const int*)d_in[7];     // (256,64,2)
    const int*   cinf = (const int*)d_in[8];     // (256,63,4)
    float* out = (float*)d_out;                  // (256,127,511)

    __half *comb, *a1h, *a2s, *b1h, *lws;
    cudaGetSymbolAddress((void**)&comb, g_comb);
    cudaGetSymbolAddress((void**)&a1h, g_a1h);
    cudaGetSymbolAddress((void**)&a2s, g_a2s);
    cudaGetSymbolAddress((void**)&b1h, g_b1h);
    cudaGetSymbolAddress((void**)&lws, g_lws);

    cudaFuncSetAttribute(mm_fp16_kernel<0>,
                         cudaFuncAttributeMaxDynamicSharedMemorySize, NSTG * STGSZ);
    cudaFuncSetAttribute(mm_fp16_kernel<1>,
                         cudaFuncAttributeMaxDynamicSharedMemorySize, NSTG * STGSZ);

    // side streams + events, created once on the (uncaptured) correctness call;
    // reused verbatim on the capture call -> parallel graph branches.
    static cudaStream_t sA = nullptr, sB = nullptr;
    static cudaEvent_t eFork = nullptr, eLws = nullptr, eB1 = nullptr;
    if (sA == nullptr) {
        cudaStreamCreateWithFlags(&sA, cudaStreamNonBlocking);
        cudaStreamCreateWithFlags(&sB, cudaStreamNonBlocking);
        cudaEventCreateWithFlags(&eFork, cudaEventDisableTiming);
        cudaEventCreateWithFlags(&eLws, cudaEventDisableTiming);
        cudaEventCreateWithFlags(&eB1, cudaEventDisableTiming);
    }

    // stream 0: init tables (needed by leaf), then fork
    init_tables_kernel<<<1, 256>>>();
    cudaEventRecord(eFork, 0);
    cudaStreamWaitEvent(sA, eFork, 0);
    cudaStreamWaitEvent(sB, eFork, 0);

    // branch A: LW spectra (needed only by GEMM2, self-contained twiddles)
    prep_lws_kernel<<<512, 128, 0, sA>>>(LW);
    cudaEventRecord(eLws, sA);

    // branch B: W transpose (needed by GEMM1)
    {
        dim3 b(32, 8);
        dim3 g(EMB / 32, HID / 32);
        prep_b1_kernel<<<g, b, 0, sB>>>(W1, W2);
    }
    cudaEventRecord(eB1, sB);

    // stream 0: seq convert (needed by GEMM1), runs concurrent with branches
    prep_a1_kernel<<<(BSZ * SEQ * EMB / 4) / 256, 256>>>(seq);

    // GEMM1 needs a1h (stream 0) + b1h (branch B)
    cudaStreamWaitEvent(0, eB1, 0);
    {
        dim3 g(HID / BN, BSZ * SEQ / BM);         // (4, 128)
        mm_fp16_kernel<0><<<g, 128, NSTG * STGSZ>>>(a1h, b1h, nullptr, comb, EMB, HID);
    }

    leaf_kernel<<<BSZ * SEQ, 128>>>(opos);
    chain_spec_kernel<<<BSZ / 2, 256>>>(cinf);

    // GEMM2 needs a2s (stream 0) + lws (branch A)
    cudaStreamWaitEvent(0, eLws, 0);
    {
        dim3 g(512 / BN, BSZ * MAXN / BM);        // (4, 254)
        mm_fp16_kernel<1><<<g, 128, NSTG * STGSZ>>>(a2s, lws, LB, out, SPH, NCAT);
    }
}